// round 4
// baseline (speedup 1.0000x reference)
#include <cuda_runtime.h>
#include <cstdint>

// ---------------- problem constants ----------------
#define CO_   1024
#define KTOT  9216
#define NXEL  6422528       // 8*1024*4*196
#define WELS  9437184       // 1024*1024*9

#define BM 128
#define BN 128
#define BK 16
#define KTILES 576          // KTOT / BK
#define STAGES 4
#define LD 20               // words per smem row (16 data + 4 pad)
#define STAGE_BYTES 10240   // 128 rows * 20 words * 4B
#define A_WORDS_STAGE 2560
#define SMEM_BYTES (2 * STAGES * STAGE_BYTES)   // 81920

// scratch (TF32-rounded)
__device__ __align__(1024) float g_Wp[CO_ * KTOT];   // [co][rr*1024+ci]
__device__ __align__(1024) float g_xt[NXEL];         // [b][t][p][ci]

__device__ __forceinline__ float f2tf32(float f) {
    uint32_t v; asm("cvt.rna.tf32.f32 %0, %1;" : "=r"(v) : "f"(f));
    return __uint_as_float(v);
}

__device__ __forceinline__ void cp16(uint32_t dst, const void* src) {
    asm volatile("cp.async.cg.shared.global [%0], [%1], 16;" :: "r"(dst), "l"(src));
}
__device__ __forceinline__ void cp16z(uint32_t dst, const void* src, int src_bytes) {
    asm volatile("cp.async.cg.shared.global [%0], [%1], 16, %2;" :: "r"(dst), "l"(src), "r"(src_bytes));
}
__device__ __forceinline__ void cp_commit() { asm volatile("cp.async.commit_group;"); }
template <int N>
__device__ __forceinline__ void cp_wait() { asm volatile("cp.async.wait_group %0;" :: "n"(N)); }

__device__ __forceinline__ void mma_tf32(float* d, const uint32_t* a, const uint32_t* b) {
    asm volatile(
        "mma.sync.aligned.m16n8k8.row.col.f32.tf32.tf32.f32 "
        "{%0,%1,%2,%3}, {%4,%5,%6,%7}, {%8,%9}, {%0,%1,%2,%3};"
        : "+f"(d[0]), "+f"(d[1]), "+f"(d[2]), "+f"(d[3])
        : "r"(a[0]), "r"(a[1]), "r"(a[2]), "r"(a[3]), "r"(b[0]), "r"(b[1]));
}

// ---------------- prep kernels (validated in R1) ----------------
__global__ void prep_w_kernel(const float* __restrict__ W) {
    __shared__ float t[1152];
    const int co = blockIdx.x;
    const int ci0 = blockIdx.y << 7;
    const int tid = threadIdx.x;
    const float4* src = reinterpret_cast<const float4*>(W + co * KTOT + ci0 * 9);
    #pragma unroll
    for (int i = tid; i < 288; i += 128) reinterpret_cast<float4*>(t)[i] = src[i];
    __syncthreads();
    for (int j = tid; j < 1152; j += 128) {
        const int rr = j >> 7, ci = j & 127;
        g_Wp[co * KTOT + rr * 1024 + ci0 + ci] = f2tf32(t[ci * 9 + rr]);
    }
}

__global__ void prep_x_kernel(const float* __restrict__ x) {
    __shared__ float tile[32][33];
    const int b = blockIdx.x >> 2, tt = blockIdx.x & 3;
    const int p0 = blockIdx.y << 5;
    const int c0 = blockIdx.z << 5;
    const int tid = threadIdx.x;
    const int j = tid & 31, i0 = tid >> 5;
    const float* src = x + ((b * 1024 + c0) * 4 + tt) * 196 + p0;
    const bool pv = (p0 + j) < 196;
    #pragma unroll
    for (int k = 0; k < 4; k++) {
        const int ci = i0 + 8 * k;
        tile[ci][j] = pv ? src[ci * 784 + j] : 0.0f;
    }
    __syncthreads();
    float* dst = g_xt + (((b * 4 + tt) * 196 + p0) * 1024) + c0;
    #pragma unroll
    for (int k = 0; k < 4; k++) {
        const int pr = i0 + 8 * k;
        if (p0 + pr < 196) dst[pr * 1024 + j] = f2tf32(tile[j][pr]);
    }
}

// ---------------- main GEMM kernel ----------------
__global__ void __launch_bounds__(128, 2) conv_mma_kernel(
    const float* __restrict__ x, float* __restrict__ out)
{
    extern __shared__ __align__(16) float sm[];
    const uint32_t sb = (uint32_t)__cvta_generic_to_shared(sm);

    const int tid  = threadIdx.x;
    const int lane = tid & 31;
    const int warp = tid >> 5;
    const int wm   = warp & 1;      // 2 warp tiles along M (64)
    const int wn   = warp >> 1;     // 2 warp tiles along N (64)
    const int r    = lane >> 2;
    const int c    = lane & 3;

    const int tileM = blockIdx.y << 7;
    const int tileN = blockIdx.x << 7;

    // ---- A gmem row for this thread ----
    const float* arow = g_Wp + (size_t)(tileM + tid) * KTOT;

    // ---- B gather setup: thread owns n = tid ----
    const int nidx = tileN + tid;
    const int nn = nidx / 3136;
    const int q1 = nidx - nn * 3136;
    const int ss = q1 / 784;
    const int q2 = q1 - ss * 784;
    const int tt = q2 / 196;
    const int pp = q2 - tt * 196;
    // base index for tap(0,0): b' = nn*4+ss-1, t' = tt-1
    const long D0 = ((long)(nn * 16 + ss * 4 + tt - 5) * 196 + pp) * 1024;
    // validity bitmask over 9 taps
    uint32_t vmask = 0;
    #pragma unroll
    for (int rr = 0; rr < 9; rr++) {
        const int ds = rr / 3, dt = rr - ds * 3;
        if ((unsigned)(ss + ds - 1) < 4u && (unsigned)(tt + dt - 1) < 4u)
            vmask |= 1u << rr;
    }

    float acc[4][8][4];
    #pragma unroll
    for (int mi = 0; mi < 4; mi++)
        #pragma unroll
        for (int ni = 0; ni < 8; ni++)
            #pragma unroll
            for (int q = 0; q < 4; q++) acc[mi][ni][q] = 0.0f;

    const uint32_t a_dst0 = sb + tid * 80;
    const uint32_t b_dst0 = sb + STAGES * STAGE_BYTES + tid * 80;

    auto load_tile = [&](int kt) {
        const int stage = kt & (STAGES - 1);
        const int k0 = kt << 4;
        // A: 4 x 16B from contiguous row
        const float* ap = arow + k0;
        const uint32_t ad = a_dst0 + stage * STAGE_BYTES;
        #pragma unroll
        for (int kc = 0; kc < 4; kc++) cp16(ad + kc * 16, ap + kc * 4);
        // B: 4 x 16B, tap constant within ktile (64 ktiles per tap)
        const int rr = kt >> 6;
        const int ds = (rr * 11) >> 5;       // rr/3
        const int dt = rr - ds * 3;
        const int pred = (vmask >> rr) & 1 ? 16 : 0;
        const int ci0 = (kt & 63) << 4;
        const float* bp = pred ? (g_xt + D0 + (ds * 4 + dt) * 200704 + ci0) : g_xt;
        const uint32_t bd = b_dst0 + stage * STAGE_BYTES;
        #pragma unroll
        for (int kc = 0; kc < 4; kc++) cp16z(bd + kc * 16, bp + kc * 4, pred);
    };

    // prefill 3 stages
    #pragma unroll
    for (int s = 0; s < STAGES - 1; s++) { load_tile(s); cp_commit(); }

    for (int kt = 0; kt < KTILES; kt++) {
        cp_wait<STAGES - 2>();
        __syncthreads();
        if (kt + STAGES - 1 < KTILES) load_tile(kt + STAGES - 1);
        cp_commit();

        const int stage = kt & (STAGES - 1);
        const float* a = sm + stage * A_WORDS_STAGE;
        const float* b = sm + STAGES * A_WORDS_STAGE + stage * A_WORDS_STAGE;
        #pragma unroll
        for (int ks = 0; ks < 2; ks++) {
            const int kk = ks * 8;
            uint32_t afr[4][4];
            uint32_t bfr[8][2];
            #pragma unroll
            for (int mi = 0; mi < 4; mi++) {
                const int m = wm * 64 + mi * 16;
                afr[mi][0] = __float_as_uint(a[(m + r    ) * LD + kk + c    ]);
                afr[mi][1] = __float_as_uint(a[(m + r + 8) * LD + kk + c    ]);
                afr[mi][2] = __float_as_uint(a[(m + r    ) * LD + kk + c + 4]);
                afr[mi][3] = __float_as_uint(a[(m + r + 8) * LD + kk + c + 4]);
            }
            #pragma unroll
            for (int ni = 0; ni < 8; ni++) {
                const int n = wn * 64 + ni * 8;
                bfr[ni][0] = __float_as_uint(b[(n + r) * LD + kk + c    ]);
                bfr[ni][1] = __float_as_uint(b[(n + r) * LD + kk + c + 4]);
            }
            #pragma unroll
            for (int mi = 0; mi < 4; mi++)
                #pragma unroll
                for (int ni = 0; ni < 8; ni++)
                    mma_tf32(acc[mi][ni], afr[mi], bfr[ni]);
        }
    }

    // ---- epilogue: fused residual, float2 stores (pairs never cross p-boundary) ----
    #pragma unroll
    for (int ni = 0; ni < 8; ni++) {
        const int col = tileN + wn * 64 + ni * 8 + 2 * c;
        const int n2 = col / 3136; const int e1 = col - n2 * 3136;
        const int s2 = e1 / 784;   const int e2 = e1 - s2 * 784;
        const int t2 = e2 / 196;   const int p2 = e2 - t2 * 196;
        // output/x layout [b8][co][t][p]: batch stride = 1024*784
        const int obase = (n2 * 4 + s2) * 1024 * 784 + t2 * 196 + p2;  // + co*784 below
        #pragma unroll
        for (int mi = 0; mi < 4; mi++) {
            const int row0 = tileM + wm * 64 + mi * 16 + r;
            const int i0 = obase + row0 * 784;
            const int i1 = i0 + 8 * 784;
            const float2 x0 = *reinterpret_cast<const float2*>(x + i0);
            const float2 x1 = *reinterpret_cast<const float2*>(x + i1);
            float2 o0, o1;
            o0.x = acc[mi][ni][0] + x0.x;  o0.y = acc[mi][ni][1] + x0.y;
            o1.x = acc[mi][ni][2] + x1.x;  o1.y = acc[mi][ni][3] + x1.y;
            *reinterpret_cast<float2*>(out + i0) = o0;
            *reinterpret_cast<float2*>(out + i1) = o1;
        }
    }
}

// ---------------- host ----------------
extern "C" void kernel_launch(void* const* d_in, const int* in_sizes, int n_in,
                              void* d_out, int out_size) {
    const float* x = (const float*)d_in[0];
    const float* W = (const float*)d_in[1];
    if (n_in >= 2 && in_sizes[0] == WELS) { const float* t = x; x = W; W = t; }

    prep_w_kernel<<<dim3(1024, 8), 128>>>(W);
    prep_x_kernel<<<dim3(32, 7, 32), 256>>>(x);

    cudaFuncSetAttribute(conv_mma_kernel, cudaFuncAttributeMaxDynamicSharedMemorySize, SMEM_BYTES);

    conv_mma_kernel<<<dim3(49, 8), 128, SMEM_BYTES>>>(x, (float*)d_out);
}